// round 14
// baseline (speedup 1.0000x reference)
#include <cuda_runtime.h>

// Problem constants
#define BB    16
#define NTOK  4096
#define PPI   256
#define NE    8
#define CCAP  640

// Scratch (device globals; no allocation allowed)
__device__ float g_gate_pos[PPI * NE];
__device__ int   g_eidx[NTOK];
__device__ float g_gate[NTOK];        // prob at argmax; zeroed by rank if dropped
__device__ float g_psum[NE];
__device__ float g_tok[NTOK * NE];    // per-token per-co ReLU sums (ungated)
__device__ unsigned g_done;           // megaconv completion counter (reset by init)

// ---------------------------------------------------------------------------
// Kernel 1: init — block 0: gate_pos table + zero psum + reset g_done;
//           blocks 1..63: bias pre-init of out (16 x 1000).
// ---------------------------------------------------------------------------
__global__ void init_kernel(const float* __restrict__ gate_w,
                            const float* __restrict__ gate_b,
                            const float* __restrict__ lb,
                            float* __restrict__ out) {
    int bid = blockIdx.x;
    int t = threadIdx.x;
    if (bid != 0) {
        int idx = (bid - 1) * 256 + t;
        if (idx < BB * 1000) {
            int b = idx / 1000, j = idx - b * 1000;
            out[b * 1000 + j] = lb[j];
        }
        return;
    }
    if (t < NE) g_psum[t] = 0.f;
    if (t == 0) g_done = 0u;
    int p = t;
    int r = p >> 4, c = p & 15;
    const float PI2 = 6.283185307179586f;
    float sgx = 0.f, s0x = 0.f, c0x = 0.f, s1x = 0.f, c1x = 0.f;
    for (int j = 0; j < 16; j++) {
        float gx = (float)(c * 16 + j) * (1.0f / 256.0f);
        sgx += gx;
        float a = PI2 * gx;
        float s_, c_;
        __sincosf(a, &s_, &c_);        s0x += s_; c0x += c_;
        __sincosf(2.f * a, &s_, &c_);  s1x += s_; c1x += c_;
    }
    float sgy = 0.f, s0y = 0.f, c0y = 0.f, s1y = 0.f, c1y = 0.f;
    for (int i = 0; i < 16; i++) {
        float gy = (float)(r * 16 + i) * (1.0f / 256.0f);
        sgy += gy;
        float a = PI2 * gy;
        float s_, c_;
        __sincosf(a, &s_, &c_);        s0y += s_; c0y += c_;
        __sincosf(2.f * a, &s_, &c_);  s1y += s_; c1y += c_;
    }
    float pcx = (c + 0.5f) / 16.f, pcy = (r + 0.5f) / 16.f;
    float spx, cpx, spy, cpy, s2px, c2px, s2py, c2py;
    __sincosf(PI2 * pcx, &spx, &cpx);
    __sincosf(PI2 * pcy, &spy, &cpy);
    __sincosf(2.f * PI2 * pcx, &s2px, &c2px);
    __sincosf(2.f * PI2 * pcy, &s2py, &c2py);
    float S[20];
    S[0]  = 16.f * sgx;    S[1]  = 16.f * sgy;
    S[2]  = 256.f * pcx;   S[3]  = 256.f * pcy;
    S[4]  = 16.f * s0x;    S[5]  = 16.f * c0x;
    S[6]  = 16.f * s0y;    S[7]  = 16.f * c0y;
    S[8]  = 256.f * spx;   S[9]  = 256.f * cpx;
    S[10] = 256.f * spy;   S[11] = 256.f * cpy;
    S[12] = 16.f * s1x;    S[13] = 16.f * c1x;
    S[14] = 16.f * s1y;    S[15] = 16.f * c1y;
    S[16] = 256.f * s2px;  S[17] = 256.f * c2px;
    S[18] = 256.f * s2py;  S[19] = 256.f * c2py;
    #pragma unroll
    for (int e = 0; e < NE; e++) {
        float acc = 0.f;
        #pragma unroll
        for (int cc = 0; cc < 20; cc++)
            acc += S[cc] * gate_w[e * 23 + 3 + cc];
        g_gate_pos[p * NE + e] = acc * (1.f / 256.f) + gate_b[e];
    }
}

// ---------------------------------------------------------------------------
// Kernel 2: megaconv — one block (128 thr) per patch; proven scalar core.
// Last-finishing block additionally runs the capacity-rank scan + aux
// (fence + done-counter idiom), eliminating the separate rank kernel.
// ---------------------------------------------------------------------------
__global__ void __launch_bounds__(128, 8) megaconv_kernel(const float* __restrict__ X,
                                                          const float* __restrict__ ew,
                                                          const float* __restrict__ eb,
                                                          const float* __restrict__ gw,
                                                          float* __restrict__ out,
                                                          int out_size) {
    __shared__ __align__(16) float sh_in[1080];   // 3 ci x 18 rows x 20 stride
    __shared__ __align__(16) float sh_wT[216];    // [k][co] transposed
    __shared__ __align__(16) float sh_b[8];
    __shared__ float s_part[4][3];
    __shared__ float s_ws[4][8];                  // [warp][co]
    __shared__ unsigned s_rank;
    __shared__ int s_cnt[8];

    int n = blockIdx.x;
    int t = threadIdx.x;
    int b = n >> 8, p = n & 255;
    int r = p >> 4, c = p & 15;
    int lane = t & 31, wid = t >> 5;

    // halo zeros (disjoint from interior; same barrier interval)
    #pragma unroll
    for (int hz = 0; hz < 2; hz++) {
        int idx = t + hz * 128;
        if (idx < 204) {
            int ci = idx / 68;
            int rem = idx - ci * 68;
            int ii, jj;
            if (rem < 18)      { ii = 0;        jj = rem; }
            else if (rem < 36) { ii = 17;       jj = rem - 18; }
            else if (rem < 52) { ii = rem - 35; jj = 0; }
            else               { ii = rem - 51; jj = 17; }
            sh_in[ci * 360 + ii * 20 + jj] = 0.f;
        }
    }

    // fill interior + channel partial sums
    const float* Xb = X + (size_t)b * 3 * 65536 + (size_t)(r * 16) * 256 + c * 16;
    int col = t & 15, rw = t >> 4;
    float sc[3] = {0.f, 0.f, 0.f};
    #pragma unroll
    for (int ci = 0; ci < 3; ci++) {
        #pragma unroll
        for (int k = 0; k < 2; k++) {
            int row = rw + k * 8;
            float v = Xb[ci * 65536 + row * 256 + col];
            sh_in[ci * 360 + (row + 1) * 20 + (col + 1)] = v;
            sc[ci] += v;
        }
    }
    #pragma unroll
    for (int ci = 0; ci < 3; ci++) {
        float v = sc[ci];
        #pragma unroll
        for (int off = 16; off; off >>= 1)
            v += __shfl_xor_sync(0xffffffffu, v, off);
        if (lane == 0) s_part[wid][ci] = v;
    }
    __syncthreads();

    // per-warp gating (redundant across warps)
    float S0 = s_part[0][0] + s_part[1][0] + s_part[2][0] + s_part[3][0];
    float S1 = s_part[0][1] + s_part[1][1] + s_part[2][1] + s_part[3][1];
    float S2 = s_part[0][2] + s_part[1][2] + s_part[2][2] + s_part[3][2];
    float lg = -1e30f;
    if (lane < NE) {
        lg = (S0 * gw[lane * 23 + 0] + S1 * gw[lane * 23 + 1] +
              S2 * gw[lane * 23 + 2]) * (1.f / 256.f)
             + g_gate_pos[p * NE + lane];
    }
    float m = lg;
    #pragma unroll
    for (int off = 4; off; off >>= 1)
        m = fmaxf(m, __shfl_xor_sync(0xffffffffu, m, off));
    float pe = (lane < NE) ? expf(lg - m) : 0.f;
    float sum = pe;
    #pragma unroll
    for (int off = 4; off; off >>= 1)
        sum += __shfl_xor_sync(0xffffffffu, sum, off);
    unsigned mk = __ballot_sync(0xffffffffu, lg == m) & 0xFFu;
    int e = __ffs(mk) - 1;      // uniform across block
    if (wid == 0) {
        if (lane < NE) atomicAdd(&g_psum[lane], pe / sum);
        if (lane == 0) { g_eidx[n] = e; g_gate[n] = 1.0f / sum; }
    }

    // load expert weights transposed: sh_wT[k*8+co]
    #pragma unroll
    for (int k2 = 0; k2 < 2; k2++) {
        int idx = t + k2 * 128;
        if (idx < 216) {
            int co = idx / 27, kk = idx - co * 27;
            sh_wT[kk * 8 + co] = ew[e * 216 + idx];
        }
    }
    if (t < 8) sh_b[t] = eb[e * 8 + t];
    __syncthreads();

    // conv: thread = 2x2 pixel block x 4 output channels; ci-outer
    int cog = t >> 6;
    int pb = t & 63;
    int R = (pb >> 3) * 2, C = (pb & 7) * 2;

    float4 b4 = ((const float4*)sh_b)[cog];
    float acc[2][2][4];
    #pragma unroll
    for (int py = 0; py < 2; py++)
        #pragma unroll
        for (int px = 0; px < 2; px++) {
            acc[py][px][0] = b4.x; acc[py][px][1] = b4.y;
            acc[py][px][2] = b4.z; acc[py][px][3] = b4.w;
        }

    #pragma unroll
    for (int ci = 0; ci < 3; ci++) {
        float in_f[4][4];
        #pragma unroll
        for (int rr = 0; rr < 4; rr++) {
            const float* base = &sh_in[ci * 360 + (R + rr) * 20 + C];
            float2 u0 = *(const float2*)(base);
            float2 u1 = *(const float2*)(base + 2);
            in_f[rr][0] = u0.x; in_f[rr][1] = u0.y;
            in_f[rr][2] = u1.x; in_f[rr][3] = u1.y;
        }
        #pragma unroll
        for (int dy = 0; dy < 3; dy++)
            #pragma unroll
            for (int dx = 0; dx < 3; dx++) {
                int kk = ci * 9 + dy * 3 + dx;
                float4 w4 = ((const float4*)sh_wT)[kk * 2 + cog];
                #pragma unroll
                for (int py = 0; py < 2; py++)
                    #pragma unroll
                    for (int px = 0; px < 2; px++) {
                        float iv = in_f[dy + py][dx + px];
                        acc[py][px][0] = fmaf(w4.x, iv, acc[py][px][0]);
                        acc[py][px][1] = fmaf(w4.y, iv, acc[py][px][1]);
                        acc[py][px][2] = fmaf(w4.z, iv, acc[py][px][2]);
                        acc[py][px][3] = fmaf(w4.w, iv, acc[py][px][3]);
                    }
            }
    }

    float v[4];
    #pragma unroll
    for (int co = 0; co < 4; co++)
        v[co] = fmaxf(acc[0][0][co], 0.f) + fmaxf(acc[0][1][co], 0.f) +
                fmaxf(acc[1][0][co], 0.f) + fmaxf(acc[1][1][co], 0.f);

    // butterfly: fold co into lane bits 4,3, reduce remaining 8 lanes
    float s0, s1, o0, o1;
    if (lane & 16) { s0 = v[2]; s1 = v[3]; o0 = v[0]; o1 = v[1]; }
    else           { s0 = v[0]; s1 = v[1]; o0 = v[2]; o1 = v[3]; }
    s0 += __shfl_xor_sync(0xffffffffu, o0, 16);
    s1 += __shfl_xor_sync(0xffffffffu, o1, 16);
    float s, o;
    if (lane & 8) { s = s1; o = s0; } else { s = s0; o = s1; }
    s += __shfl_xor_sync(0xffffffffu, o, 8);
    s += __shfl_xor_sync(0xffffffffu, s, 4);
    s += __shfl_xor_sync(0xffffffffu, s, 2);
    s += __shfl_xor_sync(0xffffffffu, s, 1);
    if ((lane & 7) == 0) {
        int co = cog * 4 + ((lane >> 4) & 1) * 2 + ((lane >> 3) & 1);
        s_ws[wid][co] = s;
    }
    __syncthreads();
    if (t < 8) {
        float tot = (t < 4) ? (s_ws[0][t] + s_ws[1][t])
                            : (s_ws[2][t] + s_ws[3][t]);
        g_tok[n * 8 + t] = tot;
    }

    // ---- last-block rank + aux (replaces rank_kernel) ----
    __threadfence();
    __syncthreads();
    if (t == 0) s_rank = atomicAdd(&g_done, 1u);
    __syncthreads();
    if (s_rank != NTOK - 1) return;
    __threadfence();   // acquire: all other blocks' writes now visible

    // 4 warps, 2 experts each (wid and wid+4); ordered ballot scan
    unsigned lmask = (1u << lane) - 1u;
    int e0 = wid, e1 = wid + 4;
    int base0 = 0, base1 = 0;
    #pragma unroll 4
    for (int tt = 0; tt < NTOK / 32; tt++) {
        int idx = tt * 32 + lane;
        int ee = g_eidx[idx];
        unsigned m0 = __ballot_sync(0xffffffffu, ee == e0);
        unsigned m1 = __ballot_sync(0xffffffffu, ee == e1);
        if (ee == e0) {
            int rank = base0 + __popc(m0 & lmask);
            if (rank >= CCAP) g_gate[idx] = 0.f;
        } else if (ee == e1) {
            int rank = base1 + __popc(m1 & lmask);
            if (rank >= CCAP) g_gate[idx] = 0.f;
        }
        base0 += __popc(m0);
        base1 += __popc(m1);
    }
    if (lane == 0) { s_cnt[e0] = base0; s_cnt[e1] = base1; }
    __syncthreads();
    if (t == 0) {
        float aux = 0.f;
        #pragma unroll
        for (int ex = 0; ex < NE; ex++) {
            float f = fminf((float)s_cnt[ex], (float)CCAP) * (1.f / (float)NTOK);
            aux += f * (g_psum[ex] * (1.f / (float)NTOK));
        }
        out[out_size - 1] = 8.f * aux;
    }
}

// ---------------------------------------------------------------------------
// Kernel 3: k-split classifier GEMM, 16-way k-split.
// grid (8 j-tiles, 4 batch-quads, 16 k-slices of 32) = 512 blocks x 128 thr.
// ---------------------------------------------------------------------------
__global__ void __launch_bounds__(128) linear_kernel(const float* __restrict__ lw,
                                                     float* __restrict__ out) {
    __shared__ __align__(16) float fs4[32][4];
    int bx = blockIdx.x, by = blockIdx.y, bz = blockIdx.z;
    int t = threadIdx.x;
    int k0 = bz * 32;

    {
        int kl = t & 31;
        int bq = t >> 5;
        int idx = k0 + kl;
        int co = idx >> 6;
        int cell = idx & 63;
        int py = cell >> 3, px = cell & 7;
        int bb = by * 4 + bq;
        float acc = 0.f;
        #pragma unroll
        for (int dy = 0; dy < 2; dy++)
            #pragma unroll
            for (int dx = 0; dx < 2; dx++) {
                int n = bb * 256 + (2 * py + dy) * 16 + (2 * px + dx);
                acc += g_tok[n * 8 + co] * g_gate[n];
            }
        fs4[kl][bq] = acc * (1.f / 1024.f);
    }
    __syncthreads();

    int j = bx * 128 + t;
    if (j < 1000) {
        const float* wp = lw + (size_t)k0 * 1000 + j;
        float a0 = 0.f, a1 = 0.f, a2 = 0.f, a3 = 0.f;
        #pragma unroll
        for (int k = 0; k < 32; k++) {
            float w = wp[(size_t)k * 1000];
            float4 f = *(const float4*)fs4[k];
            a0 = fmaf(w, f.x, a0);
            a1 = fmaf(w, f.y, a1);
            a2 = fmaf(w, f.z, a2);
            a3 = fmaf(w, f.w, a3);
        }
        int ob = by * 4;
        atomicAdd(&out[(ob + 0) * 1000 + j], a0);
        atomicAdd(&out[(ob + 1) * 1000 + j], a1);
        atomicAdd(&out[(ob + 2) * 1000 + j], a2);
        atomicAdd(&out[(ob + 3) * 1000 + j], a3);
    }
}

// ---------------------------------------------------------------------------
extern "C" void kernel_launch(void* const* d_in, const int* in_sizes, int n_in,
                              void* d_out, int out_size) {
    const float* X  = (const float*)d_in[0];
    const float* ew = (const float*)d_in[1];
    const float* eb = (const float*)d_in[2];
    const float* gw = (const float*)d_in[3];
    const float* gb = (const float*)d_in[4];
    const float* lw = (const float*)d_in[5];
    const float* lb = (const float*)d_in[6];
    float* out = (float*)d_out;

    init_kernel<<<64, 256>>>(gw, gb, lb, out);
    megaconv_kernel<<<NTOK, 128>>>(X, ew, eb, gw, out, out_size);
    dim3 g(8, 4, 16);
    linear_kernel<<<g, 128>>>(lw, out);
}

// round 15
// speedup vs baseline: 1.8750x; 1.8750x over previous
#include <cuda_runtime.h>

// Problem constants
#define BB    16
#define NTOK  4096
#define PPI   256
#define NE    8
#define CCAP  640

// Scratch (device globals; no allocation allowed)
__device__ float g_gate_pos[PPI * NE];
__device__ int   g_eidx[NTOK];
__device__ float g_gate[NTOK];        // prob at argmax; zeroed by rank if dropped
__device__ float g_psum[NE];
__device__ int   g_cnt[NE];
__device__ float g_tok[NTOK * NE];    // per-token per-co ReLU sums (ungated)

// ---------------------------------------------------------------------------
// Kernel 1: init — block 0: gate_pos table + zero psum;
//           blocks 1..63: bias pre-init of out (16 x 1000), off critical path.
// ---------------------------------------------------------------------------
__global__ void init_kernel(const float* __restrict__ gate_w,
                            const float* __restrict__ gate_b,
                            const float* __restrict__ lb,
                            float* __restrict__ out) {
    int bid = blockIdx.x;
    int t = threadIdx.x;
    if (bid != 0) {
        int idx = (bid - 1) * 256 + t;
        if (idx < BB * 1000) {
            int b = idx / 1000, j = idx - b * 1000;
            out[b * 1000 + j] = lb[j];
        }
        return;
    }
    if (t < NE) g_psum[t] = 0.f;
    int p = t;
    int r = p >> 4, c = p & 15;
    const float PI2 = 6.283185307179586f;
    float sgx = 0.f, s0x = 0.f, c0x = 0.f, s1x = 0.f, c1x = 0.f;
    for (int j = 0; j < 16; j++) {
        float gx = (float)(c * 16 + j) * (1.0f / 256.0f);
        sgx += gx;
        float a = PI2 * gx;
        float s_, c_;
        __sincosf(a, &s_, &c_);        s0x += s_; c0x += c_;
        __sincosf(2.f * a, &s_, &c_);  s1x += s_; c1x += c_;
    }
    float sgy = 0.f, s0y = 0.f, c0y = 0.f, s1y = 0.f, c1y = 0.f;
    for (int i = 0; i < 16; i++) {
        float gy = (float)(r * 16 + i) * (1.0f / 256.0f);
        sgy += gy;
        float a = PI2 * gy;
        float s_, c_;
        __sincosf(a, &s_, &c_);        s0y += s_; c0y += c_;
        __sincosf(2.f * a, &s_, &c_);  s1y += s_; c1y += c_;
    }
    float pcx = (c + 0.5f) / 16.f, pcy = (r + 0.5f) / 16.f;
    float spx, cpx, spy, cpy, s2px, c2px, s2py, c2py;
    __sincosf(PI2 * pcx, &spx, &cpx);
    __sincosf(PI2 * pcy, &spy, &cpy);
    __sincosf(2.f * PI2 * pcx, &s2px, &c2px);
    __sincosf(2.f * PI2 * pcy, &s2py, &c2py);
    float S[20];
    S[0]  = 16.f * sgx;    S[1]  = 16.f * sgy;
    S[2]  = 256.f * pcx;   S[3]  = 256.f * pcy;
    S[4]  = 16.f * s0x;    S[5]  = 16.f * c0x;
    S[6]  = 16.f * s0y;    S[7]  = 16.f * c0y;
    S[8]  = 256.f * spx;   S[9]  = 256.f * cpx;
    S[10] = 256.f * spy;   S[11] = 256.f * cpy;
    S[12] = 16.f * s1x;    S[13] = 16.f * c1x;
    S[14] = 16.f * s1y;    S[15] = 16.f * c1y;
    S[16] = 256.f * s2px;  S[17] = 256.f * c2px;
    S[18] = 256.f * s2py;  S[19] = 256.f * c2py;
    #pragma unroll
    for (int e = 0; e < NE; e++) {
        float acc = 0.f;
        #pragma unroll
        for (int cc = 0; cc < 20; cc++)
            acc += S[cc] * gate_w[e * 23 + 3 + cc];
        g_gate_pos[p * NE + e] = acc * (1.f / 256.f) + gate_b[e];
    }
}

// ---------------------------------------------------------------------------
// Kernel 2: megaconv — one block (128 thr) per patch. EXACT R11 scalar core
// (reg-budget-saturated: 64 regs x 128 thr x 8 blocks = full RF; no extras).
// ---------------------------------------------------------------------------
__global__ void __launch_bounds__(128, 8) megaconv_kernel(const float* __restrict__ X,
                                                          const float* __restrict__ ew,
                                                          const float* __restrict__ eb,
                                                          const float* __restrict__ gw) {
    __shared__ __align__(16) float sh_in[1080];   // 3 ci x 18 rows x 20 stride
    __shared__ __align__(16) float sh_wT[216];    // [k][co] transposed
    __shared__ __align__(16) float sh_b[8];
    __shared__ float s_part[4][3];
    __shared__ float s_ws[4][8];                  // [warp][co]

    int n = blockIdx.x;
    int t = threadIdx.x;
    int b = n >> 8, p = n & 255;
    int r = p >> 4, c = p & 15;
    int lane = t & 31, wid = t >> 5;

    // halo zeros (disjoint from interior; same barrier interval)
    #pragma unroll
    for (int hz = 0; hz < 2; hz++) {
        int idx = t + hz * 128;
        if (idx < 204) {
            int ci = idx / 68;
            int rem = idx - ci * 68;
            int ii, jj;
            if (rem < 18)      { ii = 0;        jj = rem; }
            else if (rem < 36) { ii = 17;       jj = rem - 18; }
            else if (rem < 52) { ii = rem - 35; jj = 0; }
            else               { ii = rem - 51; jj = 17; }
            sh_in[ci * 360 + ii * 20 + jj] = 0.f;
        }
    }

    // fill interior + channel partial sums
    const float* Xb = X + (size_t)b * 3 * 65536 + (size_t)(r * 16) * 256 + c * 16;
    int col = t & 15, rw = t >> 4;
    float sc[3] = {0.f, 0.f, 0.f};
    #pragma unroll
    for (int ci = 0; ci < 3; ci++) {
        #pragma unroll
        for (int k = 0; k < 2; k++) {
            int row = rw + k * 8;
            float v = Xb[ci * 65536 + row * 256 + col];
            sh_in[ci * 360 + (row + 1) * 20 + (col + 1)] = v;
            sc[ci] += v;
        }
    }
    #pragma unroll
    for (int ci = 0; ci < 3; ci++) {
        float v = sc[ci];
        #pragma unroll
        for (int off = 16; off; off >>= 1)
            v += __shfl_xor_sync(0xffffffffu, v, off);
        if (lane == 0) s_part[wid][ci] = v;
    }
    __syncthreads();

    // per-warp gating (redundant across warps)
    float S0 = s_part[0][0] + s_part[1][0] + s_part[2][0] + s_part[3][0];
    float S1 = s_part[0][1] + s_part[1][1] + s_part[2][1] + s_part[3][1];
    float S2 = s_part[0][2] + s_part[1][2] + s_part[2][2] + s_part[3][2];
    float lg = -1e30f;
    if (lane < NE) {
        lg = (S0 * gw[lane * 23 + 0] + S1 * gw[lane * 23 + 1] +
              S2 * gw[lane * 23 + 2]) * (1.f / 256.f)
             + g_gate_pos[p * NE + lane];
    }
    float m = lg;
    #pragma unroll
    for (int off = 4; off; off >>= 1)
        m = fmaxf(m, __shfl_xor_sync(0xffffffffu, m, off));
    float pe = (lane < NE) ? expf(lg - m) : 0.f;
    float sum = pe;
    #pragma unroll
    for (int off = 4; off; off >>= 1)
        sum += __shfl_xor_sync(0xffffffffu, sum, off);
    unsigned mk = __ballot_sync(0xffffffffu, lg == m) & 0xFFu;
    int e = __ffs(mk) - 1;      // uniform across block
    if (wid == 0) {
        if (lane < NE) atomicAdd(&g_psum[lane], pe / sum);
        if (lane == 0) { g_eidx[n] = e; g_gate[n] = 1.0f / sum; }
    }

    // load expert weights transposed: sh_wT[k*8+co]
    #pragma unroll
    for (int k2 = 0; k2 < 2; k2++) {
        int idx = t + k2 * 128;
        if (idx < 216) {
            int co = idx / 27, kk = idx - co * 27;
            sh_wT[kk * 8 + co] = ew[e * 216 + idx];
        }
    }
    if (t < 8) sh_b[t] = eb[e * 8 + t];
    __syncthreads();

    // conv: thread = 2x2 pixel block x 4 output channels; ci-outer
    int cog = t >> 6;
    int pb = t & 63;
    int R = (pb >> 3) * 2, C = (pb & 7) * 2;

    float4 b4 = ((const float4*)sh_b)[cog];
    float acc[2][2][4];
    #pragma unroll
    for (int py = 0; py < 2; py++)
        #pragma unroll
        for (int px = 0; px < 2; px++) {
            acc[py][px][0] = b4.x; acc[py][px][1] = b4.y;
            acc[py][px][2] = b4.z; acc[py][px][3] = b4.w;
        }

    #pragma unroll
    for (int ci = 0; ci < 3; ci++) {
        float in_f[4][4];
        #pragma unroll
        for (int rr = 0; rr < 4; rr++) {
            const float* base = &sh_in[ci * 360 + (R + rr) * 20 + C];
            float2 u0 = *(const float2*)(base);
            float2 u1 = *(const float2*)(base + 2);
            in_f[rr][0] = u0.x; in_f[rr][1] = u0.y;
            in_f[rr][2] = u1.x; in_f[rr][3] = u1.y;
        }
        #pragma unroll
        for (int dy = 0; dy < 3; dy++)
            #pragma unroll
            for (int dx = 0; dx < 3; dx++) {
                int kk = ci * 9 + dy * 3 + dx;
                float4 w4 = ((const float4*)sh_wT)[kk * 2 + cog];
                #pragma unroll
                for (int py = 0; py < 2; py++)
                    #pragma unroll
                    for (int px = 0; px < 2; px++) {
                        float iv = in_f[dy + py][dx + px];
                        acc[py][px][0] = fmaf(w4.x, iv, acc[py][px][0]);
                        acc[py][px][1] = fmaf(w4.y, iv, acc[py][px][1]);
                        acc[py][px][2] = fmaf(w4.z, iv, acc[py][px][2]);
                        acc[py][px][3] = fmaf(w4.w, iv, acc[py][px][3]);
                    }
            }
    }

    float v[4];
    #pragma unroll
    for (int co = 0; co < 4; co++)
        v[co] = fmaxf(acc[0][0][co], 0.f) + fmaxf(acc[0][1][co], 0.f) +
                fmaxf(acc[1][0][co], 0.f) + fmaxf(acc[1][1][co], 0.f);

    // butterfly: fold co into lane bits 4,3, reduce remaining 8 lanes
    float s0, s1, o0, o1;
    if (lane & 16) { s0 = v[2]; s1 = v[3]; o0 = v[0]; o1 = v[1]; }
    else           { s0 = v[0]; s1 = v[1]; o0 = v[2]; o1 = v[3]; }
    s0 += __shfl_xor_sync(0xffffffffu, o0, 16);
    s1 += __shfl_xor_sync(0xffffffffu, o1, 16);
    float s, o;
    if (lane & 8) { s = s1; o = s0; } else { s = s0; o = s1; }
    s += __shfl_xor_sync(0xffffffffu, o, 8);
    s += __shfl_xor_sync(0xffffffffu, s, 4);
    s += __shfl_xor_sync(0xffffffffu, s, 2);
    s += __shfl_xor_sync(0xffffffffu, s, 1);
    if ((lane & 7) == 0) {
        int co = cog * 4 + ((lane >> 4) & 1) * 2 + ((lane >> 3) & 1);
        s_ws[wid][co] = s;
    }
    __syncthreads();
    if (t < 8) {
        float tot = (t < 4) ? (s_ws[0][t] + s_ws[1][t])
                            : (s_ws[2][t] + s_ws[3][t]);
        g_tok[n * 8 + t] = tot;
    }
}

// ---------------------------------------------------------------------------
// Kernel 3: rank + aux only (out bias init moved to init_kernel). 1 block.
// ---------------------------------------------------------------------------
__global__ void rank_kernel(float* __restrict__ out, int out_size) {
    __shared__ int se[NTOK];
    int t = threadIdx.x;

    for (int i = t; i < NTOK; i += 256) se[i] = g_eidx[i];
    __syncthreads();
    int w = t >> 5, lane = t & 31;
    int base = 0;
    #pragma unroll 4
    for (int tt = 0; tt < NTOK / 32; tt++) {
        int idx = tt * 32 + lane;
        int e = se[idx];
        unsigned mask = __ballot_sync(0xffffffffu, e == w);
        if (e == w) {
            int rank = base + __popc(mask & ((1u << lane) - 1u));
            if (rank >= CCAP) g_gate[idx] = 0.f;
        }
        base += __popc(mask);
    }
    if (lane == 0) g_cnt[w] = base;
    __syncthreads();
    if (t == 0) {
        float aux = 0.f;
        #pragma unroll
        for (int e = 0; e < NE; e++) {
            float f = fminf((float)g_cnt[e], (float)CCAP) * (1.f / (float)NTOK);
            aux += f * (g_psum[e] * (1.f / (float)NTOK));
        }
        out[out_size - 1] = 8.f * aux;
    }
}

// ---------------------------------------------------------------------------
// Kernel 4: k-split classifier GEMM, 16-way k-split.
// grid (8 j-tiles, 4 batch-quads, 16 k-slices of 32) = 512 blocks x 128 thr.
// ---------------------------------------------------------------------------
__global__ void __launch_bounds__(128) linear_kernel(const float* __restrict__ lw,
                                                     float* __restrict__ out) {
    __shared__ __align__(16) float fs4[32][4];
    int bx = blockIdx.x, by = blockIdx.y, bz = blockIdx.z;
    int t = threadIdx.x;
    int k0 = bz * 32;

    {
        int kl = t & 31;
        int bq = t >> 5;
        int idx = k0 + kl;
        int co = idx >> 6;
        int cell = idx & 63;
        int py = cell >> 3, px = cell & 7;
        int bb = by * 4 + bq;
        float acc = 0.f;
        #pragma unroll
        for (int dy = 0; dy < 2; dy++)
            #pragma unroll
            for (int dx = 0; dx < 2; dx++) {
                int n = bb * 256 + (2 * py + dy) * 16 + (2 * px + dx);
                acc += g_tok[n * 8 + co] * g_gate[n];
            }
        fs4[kl][bq] = acc * (1.f / 1024.f);
    }
    __syncthreads();

    int j = bx * 128 + t;
    if (j < 1000) {
        const float* wp = lw + (size_t)k0 * 1000 + j;
        float a0 = 0.f, a1 = 0.f, a2 = 0.f, a3 = 0.f;
        #pragma unroll
        for (int k = 0; k < 32; k++) {
            float w = wp[(size_t)k * 1000];
            float4 f = *(const float4*)fs4[k];
            a0 = fmaf(w, f.x, a0);
            a1 = fmaf(w, f.y, a1);
            a2 = fmaf(w, f.z, a2);
            a3 = fmaf(w, f.w, a3);
        }
        int ob = by * 4;
        atomicAdd(&out[(ob + 0) * 1000 + j], a0);
        atomicAdd(&out[(ob + 1) * 1000 + j], a1);
        atomicAdd(&out[(ob + 2) * 1000 + j], a2);
        atomicAdd(&out[(ob + 3) * 1000 + j], a3);
    }
}

// ---------------------------------------------------------------------------
extern "C" void kernel_launch(void* const* d_in, const int* in_sizes, int n_in,
                              void* d_out, int out_size) {
    const float* X  = (const float*)d_in[0];
    const float* ew = (const float*)d_in[1];
    const float* eb = (const float*)d_in[2];
    const float* gw = (const float*)d_in[3];
    const float* gb = (const float*)d_in[4];
    const float* lw = (const float*)d_in[5];
    const float* lb = (const float*)d_in[6];
    float* out = (float*)d_out;

    init_kernel<<<64, 256>>>(gw, gb, lb, out);
    megaconv_kernel<<<NTOK, 128>>>(X, ew, eb, gw);
    rank_kernel<<<1, 256>>>(out, out_size);
    dim3 g(8, 4, 16);
    linear_kernel<<<g, 128>>>(lw, out);
}